// round 14
// baseline (speedup 1.0000x reference)
#include <cuda_runtime.h>
#include <cuda_fp16.h>
#include <cstdint>

#define PPIX 3136
#define CH 256
#define DIM 32
#define KER 7
#define K2 49
#define TILE 14
#define HALO 20
#define HALOSZ 400
#define HROW 40     // halfs per halo row (32 ch + pad), 80B, 16B-aligned
#define SROW 50     // floats per score row (49 + pad)

// scratch (allocation-free rule: device globals)
__device__ __align__(16) float  g_Qp[2 * PPIX * CH];
__device__ __align__(16) float  g_Kp[2 * PPIX * CH];
__device__ __align__(16) float  g_Vp[2 * PPIX * CH];
__device__ __align__(16) __half g_Oh[2 * PPIX * CH];   // attention output, fp16, O(1) values
__device__ __align__(16) float  g_Wt[3 * CH * CH];     // tf32-rounded Wq,Wk,Wv
__device__ __align__(16) __half g_Who[CH * CH];        // fp16 Wout
__device__ __align__(16) float  g_bcv[CH];
__device__ __align__(16) float  g_bias2[CH];           // Wout*bcv + bout

// ---------------------------------------------------------------------------
// helpers
// ---------------------------------------------------------------------------
__device__ __forceinline__ uint32_t h2_as_u32(__half2 h) {
    return *reinterpret_cast<uint32_t*>(&h);
}
__device__ __forceinline__ uint32_t f2tf(float x) {
    uint32_t r;
    asm("cvt.rna.tf32.f32 %0, %1;" : "=r"(r) : "f"(x));
    return r;
}
__device__ __forceinline__ float f2tf_f(float x) { return __uint_as_float(f2tf(x)); }
__device__ __forceinline__ void mma_tf32(float c[4], const uint32_t a[4], const uint32_t b[2]) {
    asm volatile(
        "mma.sync.aligned.m16n8k8.row.col.f32.tf32.tf32.f32 "
        "{%0,%1,%2,%3}, {%4,%5,%6,%7}, {%8,%9}, {%0,%1,%2,%3};"
        : "+f"(c[0]), "+f"(c[1]), "+f"(c[2]), "+f"(c[3])
        : "r"(a[0]), "r"(a[1]), "r"(a[2]), "r"(a[3]), "r"(b[0]), "r"(b[1]));
}
__device__ __forceinline__ void mma_f16(float c[4], const uint32_t a[4], const uint32_t b[2]) {
    asm volatile(
        "mma.sync.aligned.m16n8k16.row.col.f32.f16.f16.f32 "
        "{%0,%1,%2,%3}, {%4,%5,%6,%7}, {%8,%9}, {%0,%1,%2,%3};"
        : "+f"(c[0]), "+f"(c[1]), "+f"(c[2]), "+f"(c[3])
        : "r"(a[0]), "r"(a[1]), "r"(a[2]), "r"(a[3]), "r"(b[0]), "r"(b[1]));
}
__device__ __forceinline__ void cp16(void* smem_dst, const void* gmem_src) {
    uint32_t s = (uint32_t)__cvta_generic_to_shared(smem_dst);
    asm volatile("cp.async.cg.shared.global [%0], [%1], 16;" :: "r"(s), "l"(gmem_src));
}
#define CP_COMMIT()  asm volatile("cp.async.commit_group;")
#define CP_WAIT2()   asm volatile("cp.async.wait_group 2;")
#define CP_WAIT1()   asm volatile("cp.async.wait_group 1;")
#define CP_WAIT0()   asm volatile("cp.async.wait_group 0;")

// proj stage (floats): A_q[16][72] + A_k[16][72] + 3x B[64][20]
#define PROJ_STG (2 * 1152 + 3 * 1280)    // 6144 floats = 24.6 KB
#define OHROW 72                           // halves per outproj smem row (64 + 8 pad)
#define OUT_STGH (2 * 64 * OHROW)          // halves: A + B, BK=64

// ---------------------------------------------------------------------------
// weight convert: in_proj -> tf32 g_Wt;  out_proj -> fp16 g_Who
// ---------------------------------------------------------------------------
__global__ void w_cvt_kernel(const float* __restrict__ ipw, const float* __restrict__ opw) {
    int i = blockIdx.x * 128 + threadIdx.x;            // float4 index
    const int IPW4 = 3 * CH * CH / 4;                   // 49152
    if (i < IPW4) {
        float4 v = reinterpret_cast<const float4*>(ipw)[i];
        v.x = f2tf_f(v.x); v.y = f2tf_f(v.y); v.z = f2tf_f(v.z); v.w = f2tf_f(v.w);
        reinterpret_cast<float4*>(g_Wt)[i] = v;
    } else {
        int j = i - IPW4;                               // 0..16383
        float4 v = reinterpret_cast<const float4*>(opw)[j];
        __half2 h0 = __floats2half2_rn(v.x, v.y);
        __half2 h1 = __floats2half2_rn(v.z, v.w);
        *reinterpret_cast<uint2*>(g_Who + j * 4) = make_uint2(h2_as_u32(h0), h2_as_u32(h1));
    }
}

// ---------------------------------------------------------------------------
// bcv[c'] = pos * sum_c Wv[c'][c] + bv[c']   (V block only; K-side bias
// cancels exactly in softmax)
// ---------------------------------------------------------------------------
__global__ void bconst_kernel(const float* __restrict__ W, const float* __restrict__ b,
                              const float* __restrict__ pos) {
    int c = blockIdx.x * 8 + (threadIdx.x >> 5);
    int lane = threadIdx.x & 31;
    float p = pos[0];
    const float4* wv = reinterpret_cast<const float4*>(W + (size_t)(2 * CH + c) * CH);
    float4 v0 = wv[lane * 2], v1 = wv[lane * 2 + 1];
    float sv = v0.x + v0.y + v0.z + v0.w + v1.x + v1.y + v1.z + v1.w;
    #pragma unroll
    for (int o = 16; o > 0; o >>= 1)
        sv += __shfl_xor_sync(0xffffffffu, sv, o);
    if (lane == 0)
        g_bcv[c] = p * sv + b[2 * CH + c];
}

// ---------------------------------------------------------------------------
// bias2[c'] = sum_k Wout[c'][k] * bcv[k] + bout[c']   (fp32, exact)
// ---------------------------------------------------------------------------
__global__ void bias2_kernel(const float* __restrict__ Wout, const float* __restrict__ bout) {
    int c = blockIdx.x * 8 + (threadIdx.x >> 5);
    int lane = threadIdx.x & 31;
    const float4* wr = reinterpret_cast<const float4*>(Wout + (size_t)c * CH);
    const float4* bv = reinterpret_cast<const float4*>(g_bcv);
    float4 w0 = wr[lane * 2], w1 = wr[lane * 2 + 1];
    float4 b0 = bv[lane * 2], b1 = bv[lane * 2 + 1];
    float s = w0.x * b0.x + w0.y * b0.y + w0.z * b0.z + w0.w * b0.w
            + w1.x * b1.x + w1.y * b1.y + w1.z * b1.z + w1.w * b1.w;
    #pragma unroll
    for (int o = 16; o > 0; o >>= 1)
        s += __shfl_xor_sync(0xffffffffu, s, o);
    if (lane == 0)
        g_bias2[c] = s + bout[c];
}

// ---------------------------------------------------------------------------
// Fused Q/K/V projection (tf32, BM=64 BN=64 BK=16, cp.async 3-STAGE,
// 128 threads / 4 warps 2m x 2n warp tile 32x32, 3 CTAs/SM = 12 warps).
// Stage: A_q[16][72] | A_k[16][72] | B_q[64][20] | B_k | B_v.
// blockIdx.z = n
// ---------------------------------------------------------------------------
__global__ void __launch_bounds__(128, 3)
proj_gemm(const float* __restrict__ queries, const float* __restrict__ key,
          const float* __restrict__ bvec) {
    int n = blockIdx.z;
    const float* InQ = queries + (size_t)n * CH * PPIX;
    const float* InK = key     + (size_t)n * CH * PPIX;

    extern __shared__ float smf[];     // [3][PROJ_STG]

    int tid = threadIdx.x;
    int m0 = blockIdx.x * 64;
    int c0 = blockIdx.y * 64;
    int w = tid >> 5, lane = tid & 31;
    int r = lane >> 2, tig = lane & 3;
    int wm = (w & 1) * 32;
    int wn = (w >> 1) * 32;

    float acc[3][2][4][4] = {};

    auto issue5 = [&](int t) {
        float* base = smf + (t % 3) * PROJ_STG;
        int kt = t * 16;
        #pragma unroll
        for (int i = 0; i < 2; i++) {
            int id = tid + 128 * i;
            int row = id >> 4;                 // 0..15
            int c4 = (id & 15) * 4;            // 0..60
            cp16(base + row * 72 + c4,        InQ + (size_t)(kt + row) * PPIX + m0 + c4);
            cp16(base + 1152 + row * 72 + c4, InK + (size_t)(kt + row) * PPIX + m0 + c4);
        }
        #pragma unroll
        for (int pr = 0; pr < 3; pr++) {
            const float* W = g_Wt + (size_t)pr * CH * CH;
            float* Bs = base + 2304 + pr * 1280;
            #pragma unroll
            for (int i = 0; i < 2; i++) {
                int id = tid + 128 * i;
                int row = id >> 2;             // 0..63
                int k4 = (id & 3) * 4;         // 0..12
                cp16(Bs + row * 20 + k4, W + (size_t)(c0 + row) * CH + kt + k4);
            }
        }
        CP_COMMIT();
    };

    issue5(0);
    issue5(1);

    for (int it = 0; it < 16; it++) {
        if (it + 2 < 16) { issue5(it + 2); CP_WAIT2(); }
        else if (it + 1 < 16) { CP_WAIT1(); }
        else { CP_WAIT0(); }
        __syncthreads();                       // stage `it` visible to all

        const float* base = smf + (it % 3) * PROJ_STG;
        #pragma unroll
        for (int ks = 0; ks < 2; ks++) {
            int k0 = ks * 8;
            uint32_t aq[2][4], ak[2][4];
            #pragma unroll
            for (int mt = 0; mt < 2; mt++) {
                int m = wm + mt * 16 + r;
                aq[mt][0] = f2tf(base[(k0 + tig) * 72 + m]);
                aq[mt][1] = f2tf(base[(k0 + tig) * 72 + m + 8]);
                aq[mt][2] = f2tf(base[(k0 + tig + 4) * 72 + m]);
                aq[mt][3] = f2tf(base[(k0 + tig + 4) * 72 + m + 8]);
                ak[mt][0] = f2tf(base[1152 + (k0 + tig) * 72 + m]);
                ak[mt][1] = f2tf(base[1152 + (k0 + tig) * 72 + m + 8]);
                ak[mt][2] = f2tf(base[1152 + (k0 + tig + 4) * 72 + m]);
                ak[mt][3] = f2tf(base[1152 + (k0 + tig + 4) * 72 + m + 8]);
            }
            #pragma unroll
            for (int pr = 0; pr < 3; pr++) {
                const float* Bb = base + 2304 + pr * 1280;
                uint32_t b[4][2];
                #pragma unroll
                for (int nt = 0; nt < 4; nt++) {
                    int nn = wn + nt * 8 + r;
                    b[nt][0] = __float_as_uint(Bb[nn * 20 + k0 + tig]);
                    b[nt][1] = __float_as_uint(Bb[nn * 20 + k0 + tig + 4]);
                }
                #pragma unroll
                for (int mt = 0; mt < 2; mt++)
                    #pragma unroll
                    for (int nt = 0; nt < 4; nt++)
                        mma_tf32(acc[pr][mt][nt], (pr == 0) ? aq[mt] : ak[mt], b[nt]);
            }
        }
        __syncthreads();                       // all done reading before reissue
    }

    float* Outs[3] = { g_Qp + (size_t)n * PPIX * CH,
                       g_Kp + (size_t)n * PPIX * CH,
                       g_Vp + (size_t)n * PPIX * CH };
    #pragma unroll
    for (int pr = 0; pr < 3; pr++) {
        float* Out = Outs[pr];
        #pragma unroll
        for (int mt = 0; mt < 2; mt++) {
            int row0 = m0 + wm + mt * 16 + r;
            #pragma unroll
            for (int nt = 0; nt < 4; nt++) {
                int cc = c0 + wn + nt * 8 + 2 * tig;
                float b0 = (pr == 0) ? bvec[cc] : 0.f;
                float b1 = (pr == 0) ? bvec[cc + 1] : 0.f;
                *reinterpret_cast<float2*>(Out + (size_t)row0 * CH + cc) =
                    make_float2(acc[pr][mt][nt][0] + b0, acc[pr][mt][nt][1] + b1);
                *reinterpret_cast<float2*>(Out + (size_t)(row0 + 8) * CH + cc) =
                    make_float2(acc[pr][mt][nt][2] + b0, acc[pr][mt][nt][3] + b1);
            }
        }
    }
}

// ---------------------------------------------------------------------------
// Local attention: thread PAIR per pixel (16 channels each), 512 threads,
// fp16 K/V halos + f32 score rows in smem, 2 CTAs/SM.
// Output = pure attention average (bcv folded into bias2), fp16.
// ---------------------------------------------------------------------------
__global__ void __launch_bounds__(512, 2) attn_kernel() {
    extern __shared__ char smraw[];
    __half* Ks = reinterpret_cast<__half*>(smraw);
    __half* Vs = Ks + HALOSZ * HROW;
    float*  Ssc = reinterpret_cast<float*>(smraw + 2 * HALOSZ * HROW * sizeof(__half));

    int tx0 = blockIdx.x * TILE;
    int ty0 = blockIdx.y * TILE;
    int h = blockIdx.z & 7;
    int n = blockIdx.z >> 3;
    int tid = threadIdx.x;
    int cbase = h * DIM;

    const float* Kp = g_Kp + (size_t)n * PPIX * CH;
    const float* Vp = g_Vp + (size_t)n * PPIX * CH;

    for (int idx = tid; idx < HALOSZ * 4 * 2; idx += 512) {
        int m = idx >= HALOSZ * 4;
        int j = m ? idx - HALOSZ * 4 : idx;
        int hp = j >> 2;
        int c8 = (j & 3) * 8;
        int gy = ty0 - 3 + hp / HALO;
        int gx = tx0 - 3 + hp % HALO;
        float4 a = make_float4(0.f, 0.f, 0.f, 0.f);
        float4 b = make_float4(0.f, 0.f, 0.f, 0.f);
        if (gy >= 0 && gy < 56 && gx >= 0 && gx < 56) {
            const float* src = (m ? Vp : Kp) + (size_t)(gy * 56 + gx) * CH + cbase + c8;
            a = *reinterpret_cast<const float4*>(src);
            b = *reinterpret_cast<const float4*>(src + 4);
        }
        __half2 hh[4];
        hh[0] = __floats2half2_rn(a.x, a.y);
        hh[1] = __floats2half2_rn(a.z, a.w);
        hh[2] = __floats2half2_rn(b.x, b.y);
        hh[3] = __floats2half2_rn(b.z, b.w);
        *reinterpret_cast<uint4*>((m ? Vs : Ks) + hp * HROW + c8) =
            *reinterpret_cast<uint4*>(hh);
    }
    __syncthreads();

    if (tid >= 2 * TILE * TILE) return;
    int pix = tid >> 1;
    int half = tid & 1;
    unsigned msk = (tid < 384) ? 0xffffffffu : 0xffu;
    int ly = pix / TILE, lx = pix % TILE;
    int p = (ty0 + ly) * 56 + (tx0 + lx);
    int coff = half * 16;
    float* srow = Ssc + pix * SROW;

    const float scale = 0.17677669529663687f;
    float2 q2[8];
    {
        const float* qptr = g_Qp + (size_t)n * PPIX * CH + (size_t)p * CH + cbase + coff;
        #pragma unroll
        for (int i = 0; i < 4; i++) {
            float4 v = *reinterpret_cast<const float4*>(qptr + i * 4);
            q2[2 * i]     = make_float2(v.x * scale, v.y * scale);
            q2[2 * i + 1] = make_float2(v.z * scale, v.w * scale);
        }
    }

    float mx = -1e30f;
    #pragma unroll
    for (int ti = 0; ti < KER; ti++) {
        #pragma unroll
        for (int tj = 0; tj < KER; tj++) {
            const __half* kr = Ks + ((ly + ti) * HALO + (lx + tj)) * HROW + coff;
            __half2 hh[8];
            *reinterpret_cast<uint4*>(hh)     = *reinterpret_cast<const uint4*>(kr);
            *reinterpret_cast<uint4*>(hh + 4) = *reinterpret_cast<const uint4*>(kr + 8);
            float s0 = 0.f, s1 = 0.f;
            #pragma unroll
            for (int i = 0; i < 8; i++) {
                float2 f = __half22float2(hh[i]);
                s0 += q2[i].x * f.x;
                s1 += q2[i].y * f.y;
            }
            float s = s0 + s1;
            s += __shfl_xor_sync(msk, s, 1);
            if (half == 0) srow[ti * KER + tj] = s;
            mx = fmaxf(mx, s);
        }
    }
    __syncwarp(msk);

    float sum = 0.f;
    #pragma unroll
    for (int t = 0; t < K2; t++) {
        float wgt = __expf(srow[t] - mx);
        sum += wgt;
        if (half == 0) srow[t] = wgt;
    }
    __syncwarp(msk);
    float inv = 1.f / sum;

    float2 o2[8];
    #pragma unroll
    for (int i = 0; i < 8; i++) o2[i] = make_float2(0.f, 0.f);
    #pragma unroll
    for (int ti = 0; ti < KER; ti++) {
        #pragma unroll
        for (int tj = 0; tj < KER; tj++) {
            const __half* vr = Vs + ((ly + ti) * HALO + (lx + tj)) * HROW + coff;
            __half2 hh[8];
            *reinterpret_cast<uint4*>(hh)     = *reinterpret_cast<const uint4*>(vr);
            *reinterpret_cast<uint4*>(hh + 4) = *reinterpret_cast<const uint4*>(vr + 8);
            float wgt = srow[ti * KER + tj];
            #pragma unroll
            for (int i = 0; i < 8; i++) {
                float2 f = __half22float2(hh[i]);
                o2[i].x += wgt * f.x;
                o2[i].y += wgt * f.y;
            }
        }
    }

    // store pure attention output (O(1) values) as fp16
    __half* optr = g_Oh + (size_t)n * PPIX * CH + (size_t)p * CH + cbase + coff;
    __half2 oh[8];
    #pragma unroll
    for (int i = 0; i < 8; i++)
        oh[i] = __floats2half2_rn(o2[i].x * inv, o2[i].y * inv);
    *reinterpret_cast<uint4*>(optr)     = *reinterpret_cast<uint4*>(oh);
    *reinterpret_cast<uint4*>(optr + 8) = *reinterpret_cast<uint4*>(oh + 4);
}

// ---------------------------------------------------------------------------
// Out projection, per-batch (fp16 HMMA m16n8k16, BM=64 BN=64 BK=64, cp.async
// 2-stage, 128 threads / 4 warps 2m x 2n, 6 CTAs/SM, grid (49,4,2)):
//   out[n][c'][p] = sum_c Oh[n][p][c] * Who[c'][c] + bias2[c']
// Stage (halves): A[64][72] + B[64][72].
// ---------------------------------------------------------------------------
__global__ void __launch_bounds__(128, 6)
outproj_gemm(float* __restrict__ out) {
    extern __shared__ __half smh[];     // [2][OUT_STGH]
    int nb = blockIdx.z;
    const __half* Oh = g_Oh + (size_t)nb * PPIX * CH;

    int tid = threadIdx.x;
    int m0 = blockIdx.x * 64;
    int c0 = blockIdx.y * 64;
    int w = tid >> 5, lane = tid & 31;
    int r = lane >> 2, tig = lane & 3;
    int wm = (w & 1) * 32;
    int wn = (w >> 1) * 32;

    float acc[2][4][4] = {};

    auto issue_tile = [&](int t) {
        __half* base = smh + (t & 1) * OUT_STGH;
        int kt = t * 64;
        #pragma unroll
        for (int i = 0; i < 4; i++) {
            int id = tid + 128 * i;
            int row = id >> 3;                 // 0..63
            int k8 = (id & 7) * 8;             // 0..56
            cp16(base + row * OHROW + k8,
                 Oh + (size_t)(m0 + row) * CH + kt + k8);
            cp16(base + 64 * OHROW + row * OHROW + k8,
                 g_Who + (size_t)(c0 + row) * CH + kt + k8);
        }
        CP_COMMIT();
    };

    issue_tile(0);

    for (int it = 0; it < 4; it++) {
        if (it + 1 < 4) { issue_tile(it + 1); CP_WAIT1(); }
        else            { CP_WAIT0(); }
        __syncthreads();

        const __half* base = smh + (it & 1) * OUT_STGH;
        const __half* Bb = base + 64 * OHROW;
        #pragma unroll
        for (int ks = 0; ks < 4; ks++) {       // 4 k16-steps in BK=64
            int k0 = ks * 16;
            uint32_t a[2][4], b[4][2];
            #pragma unroll
            for (int mt = 0; mt < 2; mt++) {
                int m = wm + mt * 16 + r;
                a[mt][0] = *reinterpret_cast<const uint32_t*>(base + m * OHROW + k0 + 2 * tig);
                a[mt][1] = *reinterpret_cast<const uint32_t*>(base + (m + 8) * OHROW + k0 + 2 * tig);
                a[mt][2] = *reinterpret_cast<const uint32_t*>(base + m * OHROW + k0 + 2 * tig + 8);
                a[mt][3] = *reinterpret_cast<const uint32_t*>(base + (m + 8) * OHROW + k0 + 2 * tig + 8);
            }
            #pragma unroll
            for (int nt = 0; nt < 4; nt++) {
                int nn = wn + nt * 8 + r;
                b[nt][0] = *reinterpret_cast<const uint32_t*>(Bb + nn * OHROW + k0 + 2 * tig);
                b[nt][1] = *reinterpret_cast<const uint32_t*>(Bb + nn * OHROW + k0 + 2 * tig + 8);
            }
            #pragma unroll
            for (int mt = 0; mt < 2; mt++)
                #pragma unroll
                for (int nt = 0; nt < 4; nt++)
                    mma_f16(acc[mt][nt], a[mt], b[nt]);
        }
        __syncthreads();
    }

    // epilogue: transposed store out[c'][p], bias2 added here (exact fp32)
    float* ob = out + (size_t)nb * CH * PPIX;
    #pragma unroll
    for (int mt = 0; mt < 2; mt++) {
        int row0 = m0 + wm + mt * 16 + r;
        #pragma unroll
        for (int nt = 0; nt < 4; nt++) {
            int cc = c0 + wn + nt * 8 + 2 * tig;
            float b0 = g_bias2[cc], b1 = g_bias2[cc + 1];
            ob[(size_t)cc * PPIX + row0]           = acc[mt][nt][0] + b0;
            ob[(size_t)(cc + 1) * PPIX + row0]     = acc[mt][nt][1] + b1;
            ob[(size_t)cc * PPIX + row0 + 8]       = acc[mt][nt][2] + b0;
            ob[(size_t)(cc + 1) * PPIX + row0 + 8] = acc[mt][nt][3] + b1;
        }
    }
}

extern "C" void kernel_launch(void* const* d_in, const int* in_sizes, int n_in,
                              void* d_out, int out_size) {
    const float* queries = (const float*)d_in[0];
    const float* key     = (const float*)d_in[1];
    const float* pos     = (const float*)d_in[2];
    const float* ipw     = (const float*)d_in[3];
    const float* ipb     = (const float*)d_in[4];
    const float* opw     = (const float*)d_in[5];
    const float* opb     = (const float*)d_in[6];
    float* out = (float*)d_out;

    const int proj_smem = 3 * PROJ_STG * (int)sizeof(float);        // 73728
    const int outp_smem = 2 * OUT_STGH * (int)sizeof(__half);       // 36864
    const int attn_smem = 2 * HALOSZ * HROW * (int)sizeof(__half)
                        + TILE * TILE * SROW * (int)sizeof(float);  // 103200

    cudaFuncSetAttribute(proj_gemm,    cudaFuncAttributeMaxDynamicSharedMemorySize, proj_smem);
    cudaFuncSetAttribute(outproj_gemm, cudaFuncAttributeMaxDynamicSharedMemorySize, outp_smem);
    cudaFuncSetAttribute(attn_kernel,  cudaFuncAttributeMaxDynamicSharedMemorySize, attn_smem);

    w_cvt_kernel<<<512, 128>>>(ipw, opw);
    bconst_kernel<<<32, 256>>>(ipw, ipb, pos);
    bias2_kernel<<<32, 256>>>(opw, opb);
    proj_gemm<<<dim3(49, 4, 2), 128, proj_smem>>>(queries, key, ipb);
    attn_kernel<<<dim3(4, 4, 16), 512, attn_smem>>>();
    outproj_gemm<<<dim3(49, 4, 2), 128, outp_smem>>>(out);
}

// round 15
// speedup vs baseline: 1.1784x; 1.1784x over previous
#include <cuda_runtime.h>
#include <cuda_fp16.h>
#include <cstdint>

#define PPIX 3136
#define CH 256
#define DIM 32
#define KER 7
#define K2 49
#define TILE 14
#define HALO 20
#define HALOSZ 400
#define HROW 40     // halfs per halo row (32 ch + pad), 80B, 16B-aligned
#define SROW 50     // floats per score row (49 + pad)

// scratch (allocation-free rule: device globals)
__device__ __align__(16) __half g_Xq[2 * PPIX * CH];   // queries, (P,C) fp16
__device__ __align__(16) __half g_Xk[2 * PPIX * CH];   // key,     (P,C) fp16
__device__ __align__(16) __half g_Qh[2 * PPIX * CH];
__device__ __align__(16) __half g_Kh[2 * PPIX * CH];
__device__ __align__(16) __half g_Vh[2 * PPIX * CH];
__device__ __align__(16) __half g_Oh[2 * PPIX * CH];   // attention output
__device__ __align__(16) __half g_Whi[3 * CH * CH];    // fp16 Wq,Wk,Wv
__device__ __align__(16) __half g_Who[CH * CH];        // fp16 Wout
__device__ __align__(16) float  g_bcv[CH];
__device__ __align__(16) float  g_bias2[CH];           // Wout*bcv + bout

// ---------------------------------------------------------------------------
// helpers
// ---------------------------------------------------------------------------
__device__ __forceinline__ uint32_t h2_as_u32(__half2 h) {
    return *reinterpret_cast<uint32_t*>(&h);
}
__device__ __forceinline__ void mma_f16(float c[4], const uint32_t a[4], const uint32_t b[2]) {
    asm volatile(
        "mma.sync.aligned.m16n8k16.row.col.f32.f16.f16.f32 "
        "{%0,%1,%2,%3}, {%4,%5,%6,%7}, {%8,%9}, {%0,%1,%2,%3};"
        : "+f"(c[0]), "+f"(c[1]), "+f"(c[2]), "+f"(c[3])
        : "r"(a[0]), "r"(a[1]), "r"(a[2]), "r"(a[3]), "r"(b[0]), "r"(b[1]));
}
__device__ __forceinline__ void cp16(void* smem_dst, const void* gmem_src) {
    uint32_t s = (uint32_t)__cvta_generic_to_shared(smem_dst);
    asm volatile("cp.async.cg.shared.global [%0], [%1], 16;" :: "r"(s), "l"(gmem_src));
}
#define CP_COMMIT()  asm volatile("cp.async.commit_group;")
#define CP_WAIT1()   asm volatile("cp.async.wait_group 1;")
#define CP_WAIT0()   asm volatile("cp.async.wait_group 0;")

#define OHROW 72                     // halves per GEMM smem row (64 + 8 pad)
#define GEMM_STGH (2 * 64 * OHROW)   // halves per stage: A[64][72] + B[64][72]

// ---------------------------------------------------------------------------
// transpose + convert inputs: (n, C, P) fp32 -> (n, P, C) fp16
// 32x32 tiles through smem.  grid (98, 8, 4): z = src*2 + n
// ---------------------------------------------------------------------------
__global__ void cvt_inputs(const float* __restrict__ q, const float* __restrict__ k) {
    __shared__ float t[32][33];
    int src = blockIdx.z >> 1;
    int n   = blockIdx.z & 1;
    const float* In = (src ? k : q) + (size_t)n * CH * PPIX;
    __half* Out = (src ? g_Xk : g_Xq) + (size_t)n * PPIX * CH;
    int p0 = blockIdx.x * 32, c0 = blockIdx.y * 32;
    int tx = threadIdx.x & 31, ty = threadIdx.x >> 5;   // ty 0..7
    #pragma unroll
    for (int i = 0; i < 4; i++) {
        int c = ty + i * 8;
        t[c][tx] = In[(size_t)(c0 + c) * PPIX + p0 + tx];
    }
    __syncthreads();
    #pragma unroll
    for (int i = 0; i < 4; i++) {
        int p = ty + i * 8;
        Out[(size_t)(p0 + p) * CH + c0 + tx] = __float2half_rn(t[tx][p]);
    }
}

// ---------------------------------------------------------------------------
// weight convert: in_proj -> fp16 g_Whi;  out_proj -> fp16 g_Who
// ---------------------------------------------------------------------------
__global__ void w_cvt_kernel(const float* __restrict__ ipw, const float* __restrict__ opw) {
    int i = blockIdx.x * 128 + threadIdx.x;            // float4 index, 65536 total
    const int IPW4 = 3 * CH * CH / 4;                   // 49152
    float4 v = (i < IPW4) ? reinterpret_cast<const float4*>(ipw)[i]
                          : reinterpret_cast<const float4*>(opw)[i - IPW4];
    __half2 h0 = __floats2half2_rn(v.x, v.y);
    __half2 h1 = __floats2half2_rn(v.z, v.w);
    uint2 packed = make_uint2(h2_as_u32(h0), h2_as_u32(h1));
    if (i < IPW4) *reinterpret_cast<uint2*>(g_Whi + i * 4) = packed;
    else          *reinterpret_cast<uint2*>(g_Who + (i - IPW4) * 4) = packed;
}

// ---------------------------------------------------------------------------
// bcv[c'] = pos * sum_c Wv[c'][c] + bv[c']   (V block only; K-side bias
// cancels exactly in softmax)
// ---------------------------------------------------------------------------
__global__ void bconst_kernel(const float* __restrict__ W, const float* __restrict__ b,
                              const float* __restrict__ pos) {
    int c = blockIdx.x * 8 + (threadIdx.x >> 5);
    int lane = threadIdx.x & 31;
    float p = pos[0];
    const float4* wv = reinterpret_cast<const float4*>(W + (size_t)(2 * CH + c) * CH);
    float4 v0 = wv[lane * 2], v1 = wv[lane * 2 + 1];
    float sv = v0.x + v0.y + v0.z + v0.w + v1.x + v1.y + v1.z + v1.w;
    #pragma unroll
    for (int o = 16; o > 0; o >>= 1)
        sv += __shfl_xor_sync(0xffffffffu, sv, o);
    if (lane == 0)
        g_bcv[c] = p * sv + b[2 * CH + c];
}

// ---------------------------------------------------------------------------
// bias2[c'] = sum_k Wout[c'][k] * bcv[k] + bout[c']   (fp32, exact)
// ---------------------------------------------------------------------------
__global__ void bias2_kernel(const float* __restrict__ Wout, const float* __restrict__ bout) {
    int c = blockIdx.x * 8 + (threadIdx.x >> 5);
    int lane = threadIdx.x & 31;
    const float4* wr = reinterpret_cast<const float4*>(Wout + (size_t)c * CH);
    const float4* bv = reinterpret_cast<const float4*>(g_bcv);
    float4 w0 = wr[lane * 2], w1 = wr[lane * 2 + 1];
    float4 b0 = bv[lane * 2], b1 = bv[lane * 2 + 1];
    float s = w0.x * b0.x + w0.y * b0.y + w0.z * b0.z + w0.w * b0.w
            + w1.x * b1.x + w1.y * b1.y + w1.z * b1.z + w1.w * b1.w;
    #pragma unroll
    for (int o = 16; o > 0; o >>= 1)
        s += __shfl_xor_sync(0xffffffffu, s, o);
    if (lane == 0)
        g_bias2[c] = s + bout[c];
}

// ---------------------------------------------------------------------------
// Q/K/V projection (fp16 HMMA m16n8k16, BM=64 BN=64 BK=64, cp.async 2-stage,
// 128 threads / 4 warps 2m x 2n):  Out[p][c'] = sum_c X[p][c] * W[c'][c]
// grid (49, 4, 6): z = pr*2 + n.  Q adds bias (fp32), all outputs fp16.
// ---------------------------------------------------------------------------
__global__ void __launch_bounds__(128, 5)
proj_gemm(const float* __restrict__ ipb) {
    extern __shared__ __half smh[];     // [2][GEMM_STGH]
    int pr = blockIdx.z >> 1;
    int n  = blockIdx.z & 1;
    const __half* A = (pr == 0 ? g_Xq : g_Xk) + (size_t)n * PPIX * CH;
    const __half* B = g_Whi + (size_t)pr * CH * CH;
    __half* Out = (pr == 0 ? g_Qh : (pr == 1 ? g_Kh : g_Vh)) + (size_t)n * PPIX * CH;

    int tid = threadIdx.x;
    int m0 = blockIdx.x * 64;
    int c0 = blockIdx.y * 64;
    int w = tid >> 5, lane = tid & 31;
    int r = lane >> 2, tig = lane & 3;
    int wm = (w & 1) * 32;
    int wn = (w >> 1) * 32;

    float acc[2][4][4] = {};

    auto issue_tile = [&](int t) {
        __half* base = smh + (t & 1) * GEMM_STGH;
        int kt = t * 64;
        #pragma unroll
        for (int i = 0; i < 4; i++) {
            int id = tid + 128 * i;
            int row = id >> 3;                 // 0..63
            int k8 = (id & 7) * 8;             // 0..56
            cp16(base + row * OHROW + k8,
                 A + (size_t)(m0 + row) * CH + kt + k8);
            cp16(base + 64 * OHROW + row * OHROW + k8,
                 B + (size_t)(c0 + row) * CH + kt + k8);
        }
        CP_COMMIT();
    };

    issue_tile(0);

    for (int it = 0; it < 4; it++) {
        if (it + 1 < 4) { issue_tile(it + 1); CP_WAIT1(); }
        else            { CP_WAIT0(); }
        __syncthreads();

        const __half* base = smh + (it & 1) * GEMM_STGH;
        const __half* Bb = base + 64 * OHROW;
        #pragma unroll
        for (int ks = 0; ks < 4; ks++) {
            int k0 = ks * 16;
            uint32_t a[2][4], b[4][2];
            #pragma unroll
            for (int mt = 0; mt < 2; mt++) {
                int m = wm + mt * 16 + r;
                a[mt][0] = *reinterpret_cast<const uint32_t*>(base + m * OHROW + k0 + 2 * tig);
                a[mt][1] = *reinterpret_cast<const uint32_t*>(base + (m + 8) * OHROW + k0 + 2 * tig);
                a[mt][2] = *reinterpret_cast<const uint32_t*>(base + m * OHROW + k0 + 2 * tig + 8);
                a[mt][3] = *reinterpret_cast<const uint32_t*>(base + (m + 8) * OHROW + k0 + 2 * tig + 8);
            }
            #pragma unroll
            for (int nt = 0; nt < 4; nt++) {
                int nn = wn + nt * 8 + r;
                b[nt][0] = *reinterpret_cast<const uint32_t*>(Bb + nn * OHROW + k0 + 2 * tig);
                b[nt][1] = *reinterpret_cast<const uint32_t*>(Bb + nn * OHROW + k0 + 2 * tig + 8);
            }
            #pragma unroll
            for (int mt = 0; mt < 2; mt++)
                #pragma unroll
                for (int nt = 0; nt < 4; nt++)
                    mma_f16(acc[mt][nt], a[mt], b[nt]);
        }
        __syncthreads();
    }

    // epilogue: bias for Q (fp32 add), store fp16 half2 pairs
    #pragma unroll
    for (int mt = 0; mt < 2; mt++) {
        int row0 = m0 + wm + mt * 16 + r;
        #pragma unroll
        for (int nt = 0; nt < 4; nt++) {
            int cc = c0 + wn + nt * 8 + 2 * tig;
            float b0 = (pr == 0) ? ipb[cc] : 0.f;
            float b1 = (pr == 0) ? ipb[cc + 1] : 0.f;
            __half2 v0 = __floats2half2_rn(acc[mt][nt][0] + b0, acc[mt][nt][1] + b1);
            __half2 v1 = __floats2half2_rn(acc[mt][nt][2] + b0, acc[mt][nt][3] + b1);
            *reinterpret_cast<uint32_t*>(Out + (size_t)row0 * CH + cc)       = h2_as_u32(v0);
            *reinterpret_cast<uint32_t*>(Out + (size_t)(row0 + 8) * CH + cc) = h2_as_u32(v1);
        }
    }
}

// ---------------------------------------------------------------------------
// Local attention: thread PAIR per pixel (16 channels each), 512 threads,
// fp16 K/V halos (straight 16B copies) + f32 score rows in smem, 2 CTAs/SM.
// Output = pure attention average (bcv folded into bias2), fp16.
// ---------------------------------------------------------------------------
__global__ void __launch_bounds__(512, 2) attn_kernel() {
    extern __shared__ char smraw[];
    __half* Ks = reinterpret_cast<__half*>(smraw);
    __half* Vs = Ks + HALOSZ * HROW;
    float*  Ssc = reinterpret_cast<float*>(smraw + 2 * HALOSZ * HROW * sizeof(__half));

    int tx0 = blockIdx.x * TILE;
    int ty0 = blockIdx.y * TILE;
    int h = blockIdx.z & 7;
    int n = blockIdx.z >> 3;
    int tid = threadIdx.x;
    int cbase = h * DIM;

    const __half* Kp = g_Kh + (size_t)n * PPIX * CH;
    const __half* Vp = g_Vh + (size_t)n * PPIX * CH;

    // fill both halos: straight 16B copies (K/V already fp16), zeros for pad
    for (int idx = tid; idx < HALOSZ * 4 * 2; idx += 512) {
        int m = idx >= HALOSZ * 4;
        int j = m ? idx - HALOSZ * 4 : idx;
        int hp = j >> 2;
        int c8 = (j & 3) * 8;
        int gy = ty0 - 3 + hp / HALO;
        int gx = tx0 - 3 + hp % HALO;
        uint4 v = make_uint4(0u, 0u, 0u, 0u);
        if (gy >= 0 && gy < 56 && gx >= 0 && gx < 56)
            v = *reinterpret_cast<const uint4*>(
                (m ? Vp : Kp) + (size_t)(gy * 56 + gx) * CH + cbase + c8);
        *reinterpret_cast<uint4*>((m ? Vs : Ks) + hp * HROW + c8) = v;
    }
    __syncthreads();

    if (tid >= 2 * TILE * TILE) return;
    int pix = tid >> 1;
    int half = tid & 1;
    unsigned msk = (tid < 384) ? 0xffffffffu : 0xffu;
    int ly = pix / TILE, lx = pix % TILE;
    int p = (ty0 + ly) * 56 + (tx0 + lx);
    int coff = half * 16;
    float* srow = Ssc + pix * SROW;

    const float scale = 0.17677669529663687f;
    float2 q2[8];
    {
        const __half* qptr = g_Qh + (size_t)n * PPIX * CH + (size_t)p * CH + cbase + coff;
        __half2 qh[8];
        *reinterpret_cast<uint4*>(qh)     = *reinterpret_cast<const uint4*>(qptr);
        *reinterpret_cast<uint4*>(qh + 4) = *reinterpret_cast<const uint4*>(qptr + 8);
        #pragma unroll
        for (int i = 0; i < 8; i++) {
            float2 f = __half22float2(qh[i]);
            q2[i] = make_float2(f.x * scale, f.y * scale);
        }
    }

    float mx = -1e30f;
    #pragma unroll
    for (int ti = 0; ti < KER; ti++) {
        #pragma unroll
        for (int tj = 0; tj < KER; tj++) {
            const __half* kr = Ks + ((ly + ti) * HALO + (lx + tj)) * HROW + coff;
            __half2 hh[8];
            *reinterpret_cast<uint4*>(hh)     = *reinterpret_cast<const uint4*>(kr);
            *reinterpret_cast<uint4*>(hh + 4) = *reinterpret_cast<const uint4*>(kr + 8);
            float s0 = 0.f, s1 = 0.f;
            #pragma unroll
            for (int i = 0; i < 8; i++) {
                float2 f = __half22float2(hh[i]);
                s0 += q2[i].x * f.x;
                s1 += q2[i].y * f.y;
            }
            float s = s0 + s1;
            s += __shfl_xor_sync(msk, s, 1);
            if (half == 0) srow[ti * KER + tj] = s;
            mx = fmaxf(mx, s);
        }
    }
    __syncwarp(msk);

    float sum = 0.f;
    #pragma unroll
    for (int t = 0; t < K2; t++) {
        float wgt = __expf(srow[t] - mx);
        sum += wgt;
        if (half == 0) srow[t] = wgt;
    }
    __syncwarp(msk);
    float inv = 1.f / sum;

    float2 o2[8];
    #pragma unroll
    for (int i = 0; i < 8; i++) o2[i] = make_float2(0.f, 0.f);
    #pragma unroll
    for (int ti = 0; ti < KER; ti++) {
        #pragma unroll
        for (int tj = 0; tj < KER; tj++) {
            const __half* vr = Vs + ((ly + ti) * HALO + (lx + tj)) * HROW + coff;
            __half2 hh[8];
            *reinterpret_cast<uint4*>(hh)     = *reinterpret_cast<const uint4*>(vr);
            *reinterpret_cast<uint4*>(hh + 4) = *reinterpret_cast<const uint4*>(vr + 8);
            float wgt = srow[ti * KER + tj];
            #pragma unroll
            for (int i = 0; i < 8; i++) {
                float2 f = __half22float2(hh[i]);
                o2[i].x += wgt * f.x;
                o2[i].y += wgt * f.y;
            }
        }
    }

    __half* optr = g_Oh + (size_t)n * PPIX * CH + (size_t)p * CH + cbase + coff;
    __half2 oh[8];
    #pragma unroll
    for (int i = 0; i < 8; i++)
        oh[i] = __floats2half2_rn(o2[i].x * inv, o2[i].y * inv);
    *reinterpret_cast<uint4*>(optr)     = *reinterpret_cast<uint4*>(oh);
    *reinterpret_cast<uint4*>(optr + 8) = *reinterpret_cast<uint4*>(oh + 4);
}

// ---------------------------------------------------------------------------
// Out projection, per-batch (fp16 HMMA m16n8k16, BM=64 BN=64 BK=64, cp.async
// 2-stage, 128 threads / 4 warps 2m x 2n, grid (49,4,2)):
//   out[n][c'][p] = sum_c Oh[n][p][c] * Who[c'][c] + bias2[c']
// ---------------------------------------------------------------------------
__global__ void __launch_bounds__(128, 5)
outproj_gemm(float* __restrict__ out) {
    extern __shared__ __half smh[];     // [2][GEMM_STGH]
    int nb = blockIdx.z;
    const __half* Oh = g_Oh + (size_t)nb * PPIX * CH;

    int tid = threadIdx.x;
    int m0 = blockIdx.x * 64;
    int c0 = blockIdx.y * 64;
    int w = tid >> 5, lane = tid & 31;
    int r = lane >> 2, tig = lane & 3;
    int wm = (w & 1) * 32;
    int wn = (w >> 1) * 32;

    float acc[2][4][4] = {};

    auto issue_tile = [&](int t) {
        __half* base = smh + (t & 1) * GEMM_STGH;
        int kt = t * 64;
        #pragma unroll
        for (int i = 0; i < 4; i++) {
            int id = tid + 128 * i;
            int row = id >> 3;
            int k8 = (id & 7) * 8;
            cp16(base + row * OHROW + k8,
                 Oh + (size_t)(m0 + row) * CH + kt + k8);
            cp16(base + 64 * OHROW + row * OHROW + k8,
                 g_Who + (size_t)(c0 + row) * CH + kt + k8);
        }
        CP_COMMIT();
    };

    issue_tile(0);

    for (int it = 0; it < 4; it++) {
        if (it + 1 < 4) { issue_tile(it + 1); CP_WAIT1(); }
        else            { CP_WAIT0(); }
        __syncthreads();

        const __half* base = smh + (it & 1) * GEMM_STGH;
        const __half* Bb = base + 64 * OHROW;
        #pragma unroll
        for (int ks = 0; ks < 4; ks++) {
            int k0 = ks * 16;
            uint32_t a[2][4], b[4][2];
            #pragma unroll
            for (int mt = 0; mt < 2; mt++) {
                int m = wm + mt * 16 + r;
                a[mt][0] = *reinterpret_cast<const uint32_t*>(base + m * OHROW + k0 + 2 * tig);
                a[mt][1] = *reinterpret_cast<const uint32_t*>(base + (m + 8) * OHROW + k0 + 2 * tig);
                a[mt][2] = *reinterpret_cast<const uint32_t*>(base + m * OHROW + k0 + 2 * tig + 8);
                a[mt][3] = *reinterpret_cast<const uint32_t*>(base + (m + 8) * OHROW + k0 + 2 * tig + 8);
            }
            #pragma unroll
            for (int nt = 0; nt < 4; nt++) {
                int nn = wn + nt * 8 + r;
                b[nt][0] = *reinterpret_cast<const uint32_t*>(Bb + nn * OHROW + k0 + 2 * tig);
                b[nt][1] = *reinterpret_cast<const uint32_t*>(Bb + nn * OHROW + k0 + 2 * tig + 8);
            }
            #pragma unroll
            for (int mt = 0; mt < 2; mt++)
                #pragma unroll
                for (int nt = 0; nt < 4; nt++)
                    mma_f16(acc[mt][nt], a[mt], b[nt]);
        }
        __syncthreads();
    }

    float* ob = out + (size_t)nb * CH * PPIX;
    #pragma unroll
    for (int mt = 0; mt < 2; mt++) {
        int row0 = m0 + wm + mt * 16 + r;
        #pragma unroll
        for (int nt = 0; nt < 4; nt++) {
            int cc = c0 + wn + nt * 8 + 2 * tig;
            float b0 = g_bias2[cc], b1 = g_bias2[cc + 1];
            ob[(size_t)cc * PPIX + row0]           = acc[mt][nt][0] + b0;
            ob[(size_t)(cc + 1) * PPIX + row0]     = acc[mt][nt][1] + b1;
            ob[(size_t)cc * PPIX + row0 + 8]       = acc[mt][nt][2] + b0;
            ob[(size_t)(cc + 1) * PPIX + row0 + 8] = acc[mt][nt][3] + b1;
        }
    }
}

extern "C" void kernel_launch(void* const* d_in, const int* in_sizes, int n_in,
                              void* d_out, int out_size) {
    const float* queries = (const float*)d_in[0];
    const float* key     = (const float*)d_in[1];
    const float* pos     = (const float*)d_in[2];
    const float* ipw     = (const float*)d_in[3];
    const float* ipb     = (const float*)d_in[4];
    const float* opw     = (const float*)d_in[5];
    const float* opb     = (const float*)d_in[6];
    float* out = (float*)d_out;

    const int gemm_smem = 2 * GEMM_STGH * (int)sizeof(__half);      // 36864
    const int attn_smem = 2 * HALOSZ * HROW * (int)sizeof(__half)
                        + TILE * TILE * SROW * (int)sizeof(float);  // 103200

    cudaFuncSetAttribute(proj_gemm,    cudaFuncAttributeMaxDynamicSharedMemorySize, gemm_smem);
    cudaFuncSetAttribute(outproj_gemm, cudaFuncAttributeMaxDynamicSharedMemorySize, gemm_smem);
    cudaFuncSetAttribute(attn_kernel,  cudaFuncAttributeMaxDynamicSharedMemorySize, attn_smem);

    cvt_inputs<<<dim3(98, 8, 4), 256>>>(queries, key);
    w_cvt_kernel<<<512, 128>>>(ipw, opw);
    bconst_kernel<<<32, 256>>>(ipw, ipb, pos);
    bias2_kernel<<<32, 256>>>(opw, opb);
    proj_gemm<<<dim3(49, 4, 6), 128, gemm_smem>>>(ipb);
    attn_kernel<<<dim3(4, 4, 16), 512, attn_smem>>>();
    outproj_gemm<<<dim3(49, 4, 2), 128, gemm_smem>>>(out);
}